// round 7
// baseline (speedup 1.0000x reference)
#include <cuda_runtime.h>

#define NB   16
#define WPC  8
#define CTA_THREADS 256
#define NCTA 128          // 16 batches * 64 branches / 8 warps per CTA

__device__ float g_part[NCTA*8];
__device__ unsigned int g_ticket;

__device__ __forceinline__ float2 cmul(float2 a, float2 b){
    return make_float2(fmaf(a.x, b.x, -a.y*b.y), fmaf(a.x, b.y, a.y*b.x));
}
__device__ __forceinline__ float2 cadd(float2 a, float2 b){
    return make_float2(a.x + b.x, a.y + b.y);
}
__device__ __forceinline__ float2 shflx(float2 v, int m){
    float2 r;
    r.x = __shfl_xor_sync(0xffffffffu, v.x, m);
    r.y = __shfl_xor_sync(0xffffffffu, v.y, m);
    return r;
}

// ---------------- single-qubit gates ---------------------------------------------
__device__ __forceinline__ void sq_local(float2* a, int q,
        float2 u00, float2 u01, float2 u10, float2 u11){
    int m = 1 << q;
    #pragma unroll
    for (int i = 0; i < 8; i++){
        if (!(i & m)){
            int j = i | m;
            float2 x = a[i], y = a[j];
            a[i] = cadd(cmul(u00, x), cmul(u01, y));
            a[j] = cadd(cmul(u10, x), cmul(u11, y));
        }
    }
}
__device__ __forceinline__ void sq_lane(float2* a, int lane, int lb,
        float2 u00, float2 u01, float2 u10, float2 u11){
    int m = 1 << lb;
    bool hi = (lane >> lb) & 1;
    float2 cs = hi ? u11 : u00;
    float2 cx = hi ? u10 : u01;
    #pragma unroll
    for (int i = 0; i < 8; i++){
        float2 p = shflx(a[i], m);
        a[i] = cadd(cmul(cs, a[i]), cmul(cx, p));
    }
}

// ---------------- plain pair gates -----------------------------------------------
__device__ __forceinline__ void pair_LL(float2* a, int A, int B,
        float2 pA, float2 pB, float2 qC, float2 qD){
    int M = (1<<A) | (1<<B);
    #pragma unroll
    for (int i = 0; i < 8; i++){
        if (!((i >> B) & 1)){
            int j = i ^ M;
            bool eq = !((i >> A) & 1);
            float2 X = eq ? pA : qC;
            float2 Y = eq ? pB : qD;
            float2 ai = a[i], aj = a[j];
            a[i] = cadd(cmul(X, ai), cmul(Y, aj));
            a[j] = cadd(cmul(Y, ai), cmul(X, aj));
        }
    }
}
__device__ __forceinline__ void pair_NN(float2* a, int lane, int LA, int LB,
        float2 pA, float2 pB, float2 qC, float2 qD){
    int M = (1<<LA) | (1<<LB);
    bool eq = ((((lane >> LA) ^ (lane >> LB)) & 1) == 0);
    float2 X = eq ? pA : qC;
    float2 Y = eq ? pB : qD;
    #pragma unroll
    for (int i = 0; i < 8; i++){
        float2 p = shflx(a[i], M);
        a[i] = cadd(cmul(X, a[i]), cmul(Y, p));
    }
}
__device__ __forceinline__ void pair_ML(float2* a, int lane, int A, int LB,
        float2 pA, float2 pB, float2 qC, float2 qD){
    int lm = 1 << LB;
    int b4 = (lane >> LB) & 1;
    float2 Xi = b4 ? qC : pA, Yi = b4 ? qD : pB;
    float2 Xj = b4 ? pA : qC, Yj = b4 ? pB : qD;
    #pragma unroll
    for (int i = 0; i < 8; i++){
        if (!((i >> A) & 1)){
            int j = i | (1 << A);
            float2 pj = shflx(a[j], lm);
            float2 pi = shflx(a[i], lm);
            a[i] = cadd(cmul(Xi, a[i]), cmul(Yi, pj));
            a[j] = cadd(cmul(Xj, a[j]), cmul(Yj, pi));
        }
    }
}

// ---------------- general 4x4 gates ----------------------------------------------
// local bits 1,2 (c = bit1 + 2*bit2), group bit 0
__device__ __forceinline__ void gen_LL12(float2* a, const float2* M){
    #pragma unroll
    for (int g = 0; g < 2; g++){
        float2 i0 = a[g], i1 = a[g|2], i2 = a[g|4], i3 = a[g|6];
        a[g]   = cadd(cadd(cmul(M[0], i0), cmul(M[1], i1)), cadd(cmul(M[2], i2), cmul(M[3], i3)));
        a[g|2] = cadd(cadd(cmul(M[4], i0), cmul(M[5], i1)), cadd(cmul(M[6], i2), cmul(M[7], i3)));
        a[g|4] = cadd(cadd(cmul(M[8], i0), cmul(M[9], i1)), cadd(cmul(M[10],i2), cmul(M[11],i3)));
        a[g|6] = cadd(cadd(cmul(M[12],i0), cmul(M[13],i1)), cadd(cmul(M[14],i2), cmul(M[15],i3)));
    }
}
// lane bits LA (c bit0), LB (c bit1)
__device__ __forceinline__ void gen_NN(float2* a, int lane, int LA, int LB, const float2* M){
    int r = ((lane >> LA) & 1) | (((lane >> LB) & 1) << 1);
    float2 m0 = M[r*4 + r];
    float2 m1 = M[r*4 + (r^1)];
    float2 m2 = M[r*4 + (r^2)];
    float2 m3 = M[r*4 + (r^3)];
    int mA = 1 << LA, mB = 1 << LB;
    #pragma unroll
    for (int i = 0; i < 8; i++){
        float2 sA  = shflx(a[i], mA);
        float2 sB  = shflx(a[i], mB);
        float2 sAB = shflx(a[i], mA|mB);
        a[i] = cadd(cadd(cmul(m0, a[i]), cmul(m1, sA)), cadd(cmul(m2, sB), cmul(m3, sAB)));
    }
}

// ---------------- setup builders -------------------------------------------------
// F layout: F[0]=u00, F[1]=u01, F[2]=u10, F[3]=u11  (new0 = u00*old0 + u01*old1)
__device__ void build_ufinal4(const float* vw, float2* F){
    float s1, c1, s2, c2, sz, cz;
    __sincosf(0.5f*vw[0], &s1, &c1);
    __sincosf(0.5f*vw[1], &s2, &c2);
    __sincosf(0.5f*vw[2], &sz, &cz);
    float2 m00 = make_float2( c1*c2,  s1*s2);
    float2 m01 = make_float2(-c1*s2, -c2*s1);
    float2 m10 = make_float2( c1*s2, -c2*s1);
    float2 m11 = make_float2( c1*c2, -s1*s2);
    float2 e0 = make_float2(cz, -sz);
    float2 e1 = make_float2(cz,  sz);
    F[0] = cmul(e0, m00); F[1] = cmul(e0, m01);
    F[2] = cmul(e1, m10); F[3] = cmul(e1, m11);
}
__device__ void lcompose_rx(float2* F, float c, float s){     // F <- Rx * F
    float2 is = make_float2(0.f, -s);
    float2 n0 = cadd(make_float2(c*F[0].x, c*F[0].y), cmul(is, F[2]));
    float2 n1 = cadd(make_float2(c*F[1].x, c*F[1].y), cmul(is, F[3]));
    float2 n2 = cadd(cmul(is, F[0]), make_float2(c*F[2].x, c*F[2].y));
    float2 n3 = cadd(cmul(is, F[1]), make_float2(c*F[3].x, c*F[3].y));
    F[0]=n0; F[1]=n1; F[2]=n2; F[3]=n3;
}
__device__ void lcompose_ry(float2* F, float c, float s){     // F <- Ry * F
    float2 n0 = make_float2(fmaf(c,F[0].x,-s*F[2].x), fmaf(c,F[0].y,-s*F[2].y));
    float2 n1 = make_float2(fmaf(c,F[1].x,-s*F[3].x), fmaf(c,F[1].y,-s*F[3].y));
    float2 n2 = make_float2(fmaf(s,F[0].x, c*F[2].x), fmaf(s,F[0].y, c*F[2].y));
    float2 n3 = make_float2(fmaf(s,F[1].x, c*F[3].x), fmaf(s,F[1].y, c*F[3].y));
    F[0]=n0; F[1]=n1; F[2]=n2; F[3]=n3;
}
__device__ void build_F01q(const float* w, const float* xb, int q, float2* F){
    build_ufinal4(w + 24 + 3*q, F);
    float s, c; __sincosf(0.5f*xb[q], &s, &c);
    lcompose_rx(F, c, s);
}
// F12'' = D(v4,v5) * Ry(x) * Ufinal(L1); row1 scaled by e^{i theta}
__device__ void build_F12q(const float* w, const float* xb, const float* pw,
                           int q, int vv, float2* F){
    build_ufinal4(w + 48 + 24 + 3*q, F);
    float s, c; __sincosf(0.5f*xb[q], &s, &c);
    lcompose_ry(F, c, s);
    float s4 = (vv & 1) ? 1.f : -1.f;
    float s5 = (vv & 2) ? 1.f : -1.f;
    float th = 0.5f*(s4*pw[32 + q] + s5*pw[40 + q]);
    float sp, cp; __sincosf(th, &sp, &cp);
    float2 d = make_float2(cp, sp);
    F[2] = cmul(d, F[2]); F[3] = cmul(d, F[3]);
}
__device__ void build_F2q(const float* w, int q, float2* F){
    build_ufinal4(w + 96 + 24 + 3*q, F);
}
__device__ void paircoef(const float* w, int layer, int pidx, float2* co){
    const float* wl = w + layer*48 + 3*pidx;
    float ca, sa, cb, sb, cg, sg;
    __sincosf(0.5f*wl[0], &sa, &ca);
    __sincosf(0.5f*wl[1], &sb, &cb);
    __sincosf(0.5f*wl[2], &sg, &cg);
    float A  = ca*cb + sa*sb;
    float Bi = ca*sb - cb*sa;
    float C  = ca*cb - sa*sb;
    float Di = -(sa*cb + ca*sb);
    float2 p  = make_float2(cg, -sg);
    float2 qf = make_float2(cg,  sg);
    co[0] = make_float2(p.x*A, p.y*A);
    co[1] = cmul(p,  make_float2(0.f, Bi));
    co[2] = make_float2(qf.x*C, qf.y*C);
    co[3] = cmul(qf, make_float2(0.f, Di));
}
// M = (Fa on c-bit0  ⊗  Fb on c-bit1) · P(co), row-major M[r*4+c]
__device__ void compose44(const float2* Fa, const float2* Fb, const float2* co, float2* M){
    #pragma unroll
    for (int r = 0; r < 4; r++){
        int ra = r & 1, rb = r >> 1;
        float2 G0 = cmul(Fa[ra*2+0], Fb[rb*2+0]);
        float2 G1 = cmul(Fa[ra*2+1], Fb[rb*2+0]);
        float2 G2 = cmul(Fa[ra*2+0], Fb[rb*2+1]);
        float2 G3 = cmul(Fa[ra*2+1], Fb[rb*2+1]);
        M[r*4+0] = cadd(cmul(G0, co[0]), cmul(G3, co[1]));
        M[r*4+3] = cadd(cmul(G0, co[1]), cmul(G3, co[0]));
        M[r*4+1] = cadd(cmul(G1, co[2]), cmul(G2, co[3]));
        M[r*4+2] = cadd(cmul(G1, co[3]), cmul(G2, co[2]));
    }
}

__global__ void __launch_bounds__(CTA_THREADS, 1)
qpie_fused(const float* __restrict__ x,
           const float* __restrict__ w,
           const float* __restrict__ pw,
           float* __restrict__ out)
{
    const float c8 = 0.9238795325112867f;
    const float s8 = 0.3826834323650898f;

    __shared__ float2 sT[16];         // layer-0 record per-qubit phases
    __shared__ float2 sXcs[8];        // (cos,sin) x_q/2
    __shared__ float2 sOL[64];        // odd record lane tables (rec 2,3)
    __shared__ float2 sOLoc[16];      // odd record local tables
    __shared__ float2 sPair[48];      // plain pairs p0..p3 x 3 layers x 4 coefs
    __shared__ float2 sO0[48];        // L0 composed offset pairs (3 x 16)
    __shared__ float2 sO2[48];        // L2 composed offset pairs
    __shared__ float2 sO1[192];       // L1 composed offset pairs x 4 variants
    __shared__ float2 sFs[16];        // F01_0, F01_7, F2_0, F2_7 (4 each)
    __shared__ float2 sF12s[32];      // F12''_0 [4 var x 4], F12''_7 [4 var x 4]
    __shared__ float  sRed[64];
    __shared__ int    sLast;

    int tid  = threadIdx.x;
    int lane = tid & 31;
    int wid  = tid >> 5;
    int cta  = blockIdx.x;
    int b    = cta >> 3;
    int gw   = cta*WPC + wid;
    int br   = gw & 63;
    const float* xb = x + b*8;

    // ================= cooperative setup (146 jobs, one round) =============
    {
        int job = tid;
        if (job < 16){
            int r = job >> 3, q = job & 7;
            float s, c; __sincosf(0.5f*pw[r*8 + q], &s, &c);
            sT[r*8 + q] = make_float2(c, s);
        } else if (job < 24){
            int q = job - 16;
            float s, c; __sincosf(0.5f*xb[q], &s, &c);
            sXcs[q] = make_float2(c, s);
        } else if (job < 88){
            int k = job - 24; int r = k >> 5; int ln = k & 31;
            const float* pwa = pw + (2 + r)*8;
            float sum = 0.f;
            #pragma unroll
            for (int j = 0; j < 5; j++)
                if ((ln >> j) & 1) sum += pwa[3+j];
            float sp, cp; __sincosf(0.5f*sum, &sp, &cp);
            sOL[k] = make_float2(cp, sp);
        } else if (job < 104){
            int k = job - 88; int r = k >> 3; int i = k & 7;
            const float* pwa = pw + (2 + r)*8;
            float sum = 0.f;
            #pragma unroll
            for (int j = 0; j < 3; j++)
                if ((i >> j) & 1) sum += pwa[j];
            float sp, cp; __sincosf(0.5f*sum, &sp, &cp);
            sOLoc[k] = make_float2(cp, sp);
        } else if (job < 116){       // plain pair coefs: p0..p3 per layer
            int k = job - 104; int layer = k >> 2, p = k & 3;
            paircoef(w, layer, p, sPair + k*4);
        } else if (job < 119){       // L0 composed offset pairs
            int o = job - 116;
            float2 Fa[4], Fb[4], co[4];
            int qa = 1 + 2*o;
            build_F01q(w, xb, qa,   Fa);
            build_F01q(w, xb, qa+1, Fb);
            paircoef(w, 0, 4+o, co);
            compose44(Fa, Fb, co, sO0 + o*16);
        } else if (job < 122){       // L2 composed offset pairs
            int o = job - 119;
            float2 Fa[4], Fb[4], co[4];
            int qa = 1 + 2*o;
            build_F2q(w, qa,   Fa);
            build_F2q(w, qa+1, Fb);
            paircoef(w, 2, 4+o, co);
            compose44(Fa, Fb, co, sO2 + o*16);
        } else if (job < 134){       // L1 composed offset pairs x 4 variants
            int k = job - 122; int o = k >> 2, vv = k & 3;
            float2 Fa[4], Fb[4], co[4];
            int qa = 1 + 2*o;
            build_F12q(w, xb, pw, qa,   vv, Fa);
            build_F12q(w, xb, pw, qa+1, vv, Fb);
            paircoef(w, 1, 4+o, co);
            compose44(Fa, Fb, co, sO1 + (o*4 + vv)*16);
        } else if (job < 138){       // standalone F01_0/7, F2_0/7
            int k = job - 134;
            float2 F[4];
            if (k == 0)      build_F01q(w, xb, 0, F);
            else if (k == 1) build_F01q(w, xb, 7, F);
            else if (k == 2) build_F2q(w, 0, F);
            else             build_F2q(w, 7, F);
            sFs[k*4+0]=F[0]; sFs[k*4+1]=F[1]; sFs[k*4+2]=F[2]; sFs[k*4+3]=F[3];
        } else if (job < 146){       // F12''_0 and F12''_7 x 4 variants
            int k = job - 138; int qsel = k >> 2, vv = k & 3;
            float2 F[4];
            build_F12q(w, xb, pw, qsel ? 7 : 0, vv, F);
            float2* dst = sF12s + qsel*16 + vv*4;
            dst[0]=F[0]; dst[1]=F[1]; dst[2]=F[2]; dst[3]=F[3];
        }
    }
    __syncthreads();

    // ================= product-state init (H + Ry(x) + L0 records) =========
    // K = 1/16 (H) * 1/2 (L0 records RH^2) * 1/2 (L2 records RH^2) = 0.015625
    float2 a[8];
    {
        float sg0 = (br & 1) ? 1.f : -1.f;
        float sg1 = (br & 2) ? 1.f : -1.f;
        float2 g0[8], g1[8];
        #pragma unroll
        for (int q = 0; q < 8; q++){
            float2 t0 = sT[q], t1 = sT[8+q];
            float2 E = cmul(make_float2(t0.x, sg0*t0.y),
                            make_float2(t1.x, sg1*t1.y));
            float2 cs = sXcs[q];
            float gm = cs.x - cs.y, gp = cs.x + cs.y;
            g0[q] = make_float2(gm, 0.f);
            g1[q] = make_float2(gp*E.x, gp*E.y);
        }
        float2 lp = make_float2(0.015625f, 0.f);
        #pragma unroll
        for (int j = 0; j < 5; j++)
            lp = cmul(lp, ((lane >> j) & 1) ? g1[3+j] : g0[3+j]);
        float2 m00 = cmul(g0[0], g0[1]);
        float2 m10 = cmul(g1[0], g0[1]);
        float2 m01 = cmul(g0[0], g1[1]);
        float2 m11 = cmul(g1[0], g1[1]);
        #pragma unroll
        for (int i = 0; i < 8; i++){
            float2 mm = (i & 1) ? ((i & 2) ? m11 : m10) : ((i & 2) ? m01 : m00);
            a[i] = cmul(lp, cmul(mm, (i & 4) ? g1[2] : g0[2]));
        }
    }

    int vv = (br >> 4) & 3;

    #pragma unroll
    for (int layer = 0; layer < 3; layer++){
        // layer-1 merged odd-record diagonal (records 2,3)
        if (layer == 1){
            int v2 = (br >> 2) & 1, v3 = (br >> 3) & 1;
            float2 eL2 = sOL[lane], eL3 = sOL[32 + lane];
            int par = v2 ^ v3;
            float sgn = v2 ? -1.f : 1.f;
            #pragma unroll
            for (int i = 0; i < 8; i++){
                float2 e2 = cmul(eL2, sOLoc[i]);
                float2 e3 = cmul(eL3, sOLoc[8+i]);
                float m = (v2 ? e2.y : e2.x) * (v3 ? e3.y : e3.x);
                if (par) a[i] = make_float2(a[i].y*m, -a[i].x*m);    // * (-i m)
                else { float mm = sgn*m; a[i] = make_float2(a[i].x*mm, a[i].y*mm); }
            }
        }

        const float2* P = sPair + layer*16;
        // p0 (0,1) + CCRX
        pair_LL(a, 0, 1, P[0], P[1], P[2], P[3]);
        if ((br >> (2*layer)) & 1){
            #pragma unroll
            for (int i = 0; i < 8; i++){
                if ((i & 1) && !(i & 2)){
                    int j = i | 2;
                    float2 ai = a[i], aj = a[j];
                    a[i] = make_float2(fmaf(c8, ai.x,  s8*aj.y), fmaf(c8, ai.y, -s8*aj.x));
                    a[j] = make_float2(fmaf(c8, aj.x,  s8*ai.y), fmaf(c8, aj.y, -s8*ai.x));
                }
            }
        }
        // p1 (2,3) + CCRX
        pair_ML(a, lane, 2, 0, P[4], P[5], P[6], P[7]);
        if ((br >> (2*layer + 1)) & 1){
            #pragma unroll
            for (int i = 4; i < 8; i++){
                float2 p = shflx(a[i], 1);
                a[i] = make_float2(fmaf(c8, a[i].x,  s8*p.y), fmaf(c8, a[i].y, -s8*p.x));
            }
        }
        // p2 (4,5), p3 (6,7)
        pair_NN(a, lane, 1, 2, P[8],  P[9],  P[10], P[11]);
        pair_NN(a, lane, 3, 4, P[12], P[13], P[14], P[15]);

        // composed offset pairs (absorb fused 1q gates on q1..q6)
        const float2* O = (layer == 0) ? sO0 : (layer == 1) ? (sO1 + 0) : sO2;
        if (layer == 1){
            gen_LL12(a,          sO1 + (0*4 + vv)*16);
            gen_NN(a, lane, 0, 1, sO1 + (1*4 + vv)*16);
            gen_NN(a, lane, 2, 3, sO1 + (2*4 + vv)*16);
            // standalone F12'' on q0, q7 (4 variants)
            const float2* F0 = sF12s + vv*4;
            const float2* F7 = sF12s + 16 + vv*4;
            sq_local(a, 0, F0[0], F0[1], F0[2], F0[3]);
            sq_lane (a, lane, 4, F7[0], F7[1], F7[2], F7[3]);
        } else {
            gen_LL12(a,           O);
            gen_NN(a, lane, 0, 1, O + 16);
            gen_NN(a, lane, 2, 3, O + 32);
            const float2* F0 = (layer == 0) ? (sFs + 0) : (sFs + 8);
            const float2* F7 = (layer == 0) ? (sFs + 4) : (sFs + 12);
            sq_local(a, 0, F0[0], F0[1], F0[2], F0[3]);
            sq_lane (a, lane, 4, F7[0], F7[1], F7[2], F7[3]);
        }
    }

    // ================= measurement & fused reduction =======================
    float e[8];
    float tot = 0.f;
    #pragma unroll
    for (int q = 0; q < 3; q++) e[q] = 0.f;
    #pragma unroll
    for (int i = 0; i < 8; i++){
        float p = fmaf(a[i].x, a[i].x, a[i].y*a[i].y);
        tot += p;
        #pragma unroll
        for (int q = 0; q < 3; q++)
            e[q] += ((i >> q) & 1) ? -p : p;
    }
    #pragma unroll
    for (int q = 0; q < 5; q++)
        e[3+q] = ((lane >> q) & 1) ? -tot : tot;

    #pragma unroll
    for (int q = 0; q < 8; q++){
        #pragma unroll
        for (int s = 16; s; s >>= 1)
            e[q] += __shfl_xor_sync(0xffffffffu, e[q], s);
    }
    if (lane == 0){
        #pragma unroll
        for (int q = 0; q < 8; q++) sRed[wid*8 + q] = e[q];
    }
    __syncthreads();

    if (tid < 8){
        float s = 0.f;
        #pragma unroll
        for (int wq = 0; wq < 8; wq++) s += sRed[wq*8 + tid];
        g_part[cta*8 + tid] = s;
        __threadfence();
    }
    __syncthreads();

    if (tid == 0){
        __threadfence();
        unsigned int t = atomicAdd(&g_ticket, 1u);
        sLast = (t == NCTA - 1) ? 1 : 0;
    }
    __syncthreads();

    if (sLast){
        __threadfence();
        if (tid < 128){
            int bb = tid >> 3, q = tid & 7;
            float s = 0.f;
            #pragma unroll
            for (int k = 0; k < 8; k++)
                s += g_part[(bb*8 + k)*8 + q];
            out[tid] = s;
        }
        __syncthreads();
        if (tid == 0) g_ticket = 0;
    }
}

extern "C" void kernel_launch(void* const* d_in, const int* in_sizes, int n_in,
                              void* d_out, int out_size){
    const float* x  = (const float*)d_in[0];   // (16, 8)
    const float* w  = (const float*)d_in[1];   // (3, 48)
    const float* pw = (const float*)d_in[2];   // (3, 2, 8)
    float* out = (float*)d_out;                // (16, 8)

    qpie_fused<<<NCTA, CTA_THREADS>>>(x, w, pw, out);
}